// round 6
// baseline (speedup 1.0000x reference)
#include <cuda_runtime.h>
#include <cuda_bf16.h>
#include <cstdint>

// B=16, TQ=TP=DQ=DP=1024
// out = softmax_over_Tp((p@W)@q^T) @ q, fp32 in/out.
// GEMMs: mma.sync.m16n8k16 bf16, 2-way split, 3 products (hh+hl+lh).
// 128x128x64 CTA tile, 512 threads = 16 warps (2m x 4n x 2kg), warp tile 64x32,
// warp-level split-K2 with smem reduction, 3-stage cp.async pipeline.

static const long TT = 1048576L;

// ---------------- scratch ----------------
__device__ __nv_bfloat16 g_qhi[16777216], g_qlo[16777216];
__device__ __nv_bfloat16 g_phi[16777216], g_plo[16777216];
__device__ __nv_bfloat16 g_qThi[16777216], g_qTlo[16777216];
__device__ __nv_bfloat16 g_Wthi[1048576],  g_Wtlo[1048576];
__device__ __nv_bfloat16 g_pWhi[16777216], g_pWlo[16777216];
__device__ __nv_bfloat16 g_Ehi[16777216],  g_Elo[16777216];
__device__ float g_S[16777216];

// ---------------- asm helpers ----------------
__device__ __forceinline__ uint32_t smem_u32(const void* p) {
    uint32_t a;
    asm("{ .reg .u64 t; cvta.to.shared.u64 t, %1; cvt.u32.u64 %0, t; }" : "=r"(a) : "l"(p));
    return a;
}
__device__ __forceinline__ void cp16(uint32_t s, const void* g) {
    asm volatile("cp.async.cg.shared.global [%0], [%1], 16;" :: "r"(s), "l"(g));
}
__device__ __forceinline__ void cp_commit() { asm volatile("cp.async.commit_group;"); }
template<int N>
__device__ __forceinline__ void cp_wait() { asm volatile("cp.async.wait_group %0;" :: "n"(N)); }

__device__ __forceinline__ void ldsm4(uint32_t (&r)[4], uint32_t a) {
    asm volatile("ldmatrix.sync.aligned.m8n8.x4.shared.b16 {%0,%1,%2,%3}, [%4];"
                 : "=r"(r[0]), "=r"(r[1]), "=r"(r[2]), "=r"(r[3]) : "r"(a));
}
__device__ __forceinline__ void mma16816(float (&d)[4], const uint32_t (&a)[4],
                                         uint32_t b0, uint32_t b1) {
    asm volatile(
        "mma.sync.aligned.m16n8k16.row.col.f32.bf16.bf16.f32 "
        "{%0,%1,%2,%3}, {%4,%5,%6,%7}, {%8,%9}, {%0,%1,%2,%3};"
        : "+f"(d[0]), "+f"(d[1]), "+f"(d[2]), "+f"(d[3])
        : "r"(a[0]), "r"(a[1]), "r"(a[2]), "r"(a[3]), "r"(b0), "r"(b1));
}

// ---------------- GEMM: C[b][m][n] = sum_k A[b][m][k] * B[b][n][k] ----------------
static constexpr int MATB   = 128 * 128;   // 16KB per matrix tile (128 rows x 128B)
static constexpr int STAGEB = 4 * MATB;    // Ahi,Alo,Bhi,Blo = 64KB
static constexpr int SMEMSZ = 3 * STAGEB;  // 192KB (also holds 64KB reduce buffer)

template<int STORE_SPLIT>
__global__ void __launch_bounds__(512, 1)
gemm_mma(const __nv_bfloat16* __restrict__ Ahi, const __nv_bfloat16* __restrict__ Alo, long sA,
         const __nv_bfloat16* __restrict__ Bhi, const __nv_bfloat16* __restrict__ Blo, long sB,
         float* __restrict__ Cf, __nv_bfloat16* __restrict__ Chi, __nv_bfloat16* __restrict__ Clo)
{
    extern __shared__ char smem[];
    const uint32_t sbase = smem_u32(smem);
    const int tid = threadIdx.x, lane = tid & 31, wid = tid >> 5;
    const int kg = wid >> 3;                  // k-group 0/1
    const int w8 = wid & 7;                  // warp within k-group
    const int wm = w8 >> 2, wn = w8 & 3;     // 2m x 4n grid of 64x32 warp tiles
    const int b = blockIdx.z, m0 = blockIdx.y * 128, n0 = blockIdx.x * 128;

    const char* gA[2] = { (const char*)(Ahi + (size_t)b * sA + (size_t)m0 * 1024),
                          (const char*)(Alo + (size_t)b * sA + (size_t)m0 * 1024) };
    const char* gB[2] = { (const char*)(Bhi + (size_t)b * sB + (size_t)n0 * 1024),
                          (const char*)(Blo + (size_t)b * sB + (size_t)n0 * 1024) };

    // loader: per matrix 1024 x 16B chunks, thread handles 2 (tid, tid+512)
    const int crow[2] = { tid >> 3, (tid + 512) >> 3 };
    const int ccol = tid & 7;

    auto issue_stage = [&](int buf, int kt) {
        const uint32_t sb = sbase + buf * STAGEB;
        const size_t kb = (size_t)kt * 128;
        #pragma unroll
        for (int m = 0; m < 4; m++) {
            const char* g = (m < 2) ? gA[m] : gB[m - 2];
            const uint32_t mb = sb + m * MATB;
            #pragma unroll
            for (int t = 0; t < 2; t++) {
                const int r = crow[t];
                cp16(mb + r * 128 + ((ccol ^ (r & 7)) * 16),
                     g + (size_t)r * 2048 + kb + ccol * 16);
            }
        }
        cp_commit();
    };

    float acc[4][4][4];
    #pragma unroll
    for (int i = 0; i < 4; i++)
        #pragma unroll
        for (int j = 0; j < 4; j++)
            #pragma unroll
            for (int t = 0; t < 4; t++) acc[i][j][t] = 0.f;

    issue_stage(0, 0);
    issue_stage(1, 1);

    // ldmatrix lane addressing
    const int lrow = lane & 15, lhi = lane >> 4;
    const int swz = lrow & 7;
    uint32_t koff[4];
    #pragma unroll
    for (int ks = 0; ks < 4; ks++) koff[ks] = (uint32_t)(((ks * 2 + lhi) ^ swz) * 16);

    const uint32_t arow_off = (uint32_t)(wm * 64 + lrow) * 128;
    const uint32_t brow_off = (uint32_t)(wn * 32 + lrow) * 128;

    #pragma unroll 1
    for (int i = 0; i < 16; i++) {
        if (i < 15) cp_wait<1>(); else cp_wait<0>();
        __syncthreads();
        if (i + 2 < 16) issue_stage((i + 2) % 3, i + 2);

        const uint32_t sb = sbase + (i % 3) * STAGEB;
        const uint32_t sAh = sb, sAl = sb + MATB, sBh = sb + 2 * MATB, sBl = sb + 3 * MATB;

        #pragma unroll
        for (int ks2 = 0; ks2 < 2; ks2++) {
            const uint32_t kb = koff[kg * 2 + ks2];
            // product 1: hh
            uint32_t ah[4][4];
            #pragma unroll
            for (int mi = 0; mi < 4; mi++)
                ldsm4(ah[mi], sAh + arow_off + (uint32_t)(mi * 16) * 128 + kb);
            uint32_t bh[4][2];
            #pragma unroll
            for (int nj = 0; nj < 2; nj++) {
                uint32_t r[4];
                ldsm4(r, sBh + brow_off + (uint32_t)(nj * 16) * 128 + kb);
                bh[2*nj][0] = r[0]; bh[2*nj+1][0] = r[1];
                bh[2*nj][1] = r[2]; bh[2*nj+1][1] = r[3];
            }
            #pragma unroll
            for (int mi = 0; mi < 4; mi++)
                #pragma unroll
                for (int ni = 0; ni < 4; ni++)
                    mma16816(acc[mi][ni], ah[mi], bh[ni][0], bh[ni][1]);
            // product 2: hl (reuse ah)
            uint32_t bl[4][2];
            #pragma unroll
            for (int nj = 0; nj < 2; nj++) {
                uint32_t r[4];
                ldsm4(r, sBl + brow_off + (uint32_t)(nj * 16) * 128 + kb);
                bl[2*nj][0] = r[0]; bl[2*nj+1][0] = r[1];
                bl[2*nj][1] = r[2]; bl[2*nj+1][1] = r[3];
            }
            #pragma unroll
            for (int mi = 0; mi < 4; mi++)
                #pragma unroll
                for (int ni = 0; ni < 4; ni++)
                    mma16816(acc[mi][ni], ah[mi], bl[ni][0], bl[ni][1]);
            // product 3: lh (reuse bh)
            uint32_t al[4][4];
            #pragma unroll
            for (int mi = 0; mi < 4; mi++)
                ldsm4(al[mi], sAl + arow_off + (uint32_t)(mi * 16) * 128 + kb);
            #pragma unroll
            for (int mi = 0; mi < 4; mi++)
                #pragma unroll
                for (int ni = 0; ni < 4; ni++)
                    mma16816(acc[mi][ni], al[mi], bh[ni][0], bh[ni][1]);
        }
    }

    // ---------------- split-K reduction (kg1 -> smem, kg0 adds) ----------------
    __syncthreads();
    float* red = (float*)smem;
    if (kg == 1) {
        float* base = red + (size_t)w8 * 2048;
        const float* af = (const float*)acc;
        #pragma unroll
        for (int t = 0; t < 64; t++) base[t * 32 + lane] = af[t];
    }
    __syncthreads();
    if (kg == 0) {
        const float* base = red + (size_t)w8 * 2048;
        float* af = (float*)acc;
        #pragma unroll
        for (int t = 0; t < 64; t++) af[t] += base[t * 32 + lane];

        // epilogue store
        const int er = m0 + wm * 64 + (lane >> 2);
        const int ec = n0 + wn * 32 + (lane & 3) * 2;
        #pragma unroll
        for (int mi = 0; mi < 4; mi++)
            #pragma unroll
            for (int ni = 0; ni < 4; ni++) {
                const int r0 = er + mi * 16, c = ec + ni * 8;
                const size_t o0 = (size_t)b * TT + (size_t)r0 * 1024 + c;
                const size_t o1 = o0 + 8 * 1024;
                if (STORE_SPLIT == 0) {
                    *(float2*)(Cf + o0) = make_float2(acc[mi][ni][0], acc[mi][ni][1]);
                    *(float2*)(Cf + o1) = make_float2(acc[mi][ni][2], acc[mi][ni][3]);
                } else {
                    #pragma unroll
                    for (int h = 0; h < 2; h++) {
                        const size_t o = h ? o1 : o0;
                        float x0 = acc[mi][ni][2*h], x1 = acc[mi][ni][2*h+1];
                        __nv_bfloat16 h0 = __float2bfloat16(x0);
                        __nv_bfloat16 h1 = __float2bfloat16(x1);
                        __nv_bfloat16 l0 = __float2bfloat16(x0 - __bfloat162float(h0));
                        __nv_bfloat16 l1 = __float2bfloat16(x1 - __bfloat162float(h1));
                        __nv_bfloat162 hp; hp.x = h0; hp.y = h1;
                        __nv_bfloat162 lp; lp.x = l0; lp.y = l1;
                        *(__nv_bfloat162*)(Chi + o) = hp;
                        *(__nv_bfloat162*)(Clo + o) = lp;
                    }
                }
            }
    }
}

// ---------------- elementwise / transpose / softmax ----------------
struct alignas(8) bh4 { __nv_bfloat16 a, b, c, d; };

__device__ __forceinline__ void split1(float x, __nv_bfloat16& h, __nv_bfloat16& l) {
    h = __float2bfloat16(x);
    l = __float2bfloat16(x - __bfloat162float(h));
}

__global__ void __launch_bounds__(256)
split2_kernel(const float* __restrict__ X, __nv_bfloat16* __restrict__ hi,
              __nv_bfloat16* __restrict__ lo)
{
    size_t i = (size_t)blockIdx.x * 256 + threadIdx.x;
    float4 v = ((const float4*)X)[i];
    bh4 h, l;
    split1(v.x, h.a, l.a); split1(v.y, h.b, l.b);
    split1(v.z, h.c, l.c); split1(v.w, h.d, l.d);
    ((bh4*)hi)[i] = h;
    ((bh4*)lo)[i] = l;
}

__global__ void __launch_bounds__(256)
split_both_kernel(const float* __restrict__ in,
                  __nv_bfloat16* __restrict__ ohi, __nv_bfloat16* __restrict__ olo,
                  __nv_bfloat16* __restrict__ thi, __nv_bfloat16* __restrict__ tlo)
{
    __shared__ float t[32][33];
    const int b = blockIdx.z;
    const float* I = in + (size_t)b * TT;
    const int x = blockIdx.x * 32 + threadIdx.x;
    const int y = blockIdx.y * 32 + threadIdx.y;
    const size_t ob = (size_t)b * TT;
    #pragma unroll
    for (int j = 0; j < 32; j += 8) {
        float v = I[(size_t)(y + j) * 1024 + x];
        t[threadIdx.y + j][threadIdx.x] = v;
        __nv_bfloat16 h, l; split1(v, h, l);
        ohi[ob + (size_t)(y + j) * 1024 + x] = h;
        olo[ob + (size_t)(y + j) * 1024 + x] = l;
    }
    __syncthreads();
    const int ox = blockIdx.y * 32 + threadIdx.x;
    const int oy = blockIdx.x * 32 + threadIdx.y;
    #pragma unroll
    for (int j = 0; j < 32; j += 8) {
        float v = t[threadIdx.x][threadIdx.y + j];
        __nv_bfloat16 h, l; split1(v, h, l);
        thi[ob + (size_t)(oy + j) * 1024 + ox] = h;
        tlo[ob + (size_t)(oy + j) * 1024 + ox] = l;
    }
}

__global__ void __launch_bounds__(256)
transpose_split_kernel(const float* __restrict__ in, __nv_bfloat16* __restrict__ ohi,
                       __nv_bfloat16* __restrict__ olo)
{
    __shared__ float t[32][33];
    const int b = blockIdx.z;
    const float* I = in + (size_t)b * TT;
    const int x = blockIdx.x * 32 + threadIdx.x;
    const int y = blockIdx.y * 32 + threadIdx.y;
    #pragma unroll
    for (int j = 0; j < 32; j += 8)
        t[threadIdx.y + j][threadIdx.x] = I[(size_t)(y + j) * 1024 + x];
    __syncthreads();
    const int ox = blockIdx.y * 32 + threadIdx.x;
    const int oy = blockIdx.x * 32 + threadIdx.y;
    const size_t ob = (size_t)b * TT;
    #pragma unroll
    for (int j = 0; j < 32; j += 8) {
        float v = t[threadIdx.x][threadIdx.y + j];
        __nv_bfloat16 h, l; split1(v, h, l);
        ohi[ob + (size_t)(oy + j) * 1024 + ox] = h;
        olo[ob + (size_t)(oy + j) * 1024 + ox] = l;
    }
}

// Fused column softmax (over Tp = rows of S[b]) + exp + bf16 split.
__global__ void __launch_bounds__(256)
softmax_exp_split(const float* __restrict__ S,
                  __nv_bfloat16* __restrict__ Ehi, __nv_bfloat16* __restrict__ Elo)
{
    __shared__ float sm[8][32], sz[8][32];
    __shared__ float fm[32], fz[32];
    const int b = blockIdx.y;
    const int c = (threadIdx.x & 31);
    const int g = threadIdx.x >> 5;
    const int col = blockIdx.x * 32 + c;
    const float* Sb = S + (size_t)b * TT + col;

    float m = -1e30f, z = 0.f;
    #pragma unroll 4
    for (int r = g; r < 1024; r += 8) {
        float x = Sb[(size_t)r << 10];
        if (x > m) { z = z * __expf(m - x) + 1.f; m = x; }
        else       { z += __expf(x - m); }
    }
    sm[g][c] = m; sz[g][c] = z;
    __syncthreads();
    if (threadIdx.x < 32) {
        float M = sm[0][c];
        #pragma unroll
        for (int i = 1; i < 8; i++) M = fmaxf(M, sm[i][c]);
        float Z = 0.f;
        #pragma unroll
        for (int i = 0; i < 8; i++) Z += sz[i][c] * __expf(sm[i][c] - M);
        fm[c] = M; fz[c] = 1.0f / Z;
    }
    __syncthreads();
    const float Mf = fm[c], Rf = fz[c];
    __nv_bfloat16* eh = Ehi + (size_t)b * TT + col;
    __nv_bfloat16* el = Elo + (size_t)b * TT + col;
    #pragma unroll 4
    for (int r = g; r < 1024; r += 8) {
        float x = Sb[(size_t)r << 10];
        float w = __expf(x - Mf) * Rf;
        __nv_bfloat16 h, l; split1(w, h, l);
        eh[(size_t)r << 10] = h;
        el[(size_t)r << 10] = l;
    }
}

// ---------------- launcher ----------------
extern "C" void kernel_launch(void* const* d_in, const int* in_sizes, int n_in,
                              void* d_out, int out_size)
{
    const float* q = (const float*)d_in[0];
    const float* p = (const float*)d_in[1];
    const float* W = (const float*)d_in[2];
    float* out = (float*)d_out;

    __nv_bfloat16 *qhi, *qlo, *phi, *plo, *qThi, *qTlo, *Wthi, *Wtlo, *pWhi, *pWlo, *Ehi, *Elo;
    float *S;
    cudaGetSymbolAddress((void**)&qhi, g_qhi);   cudaGetSymbolAddress((void**)&qlo, g_qlo);
    cudaGetSymbolAddress((void**)&phi, g_phi);   cudaGetSymbolAddress((void**)&plo, g_plo);
    cudaGetSymbolAddress((void**)&qThi, g_qThi); cudaGetSymbolAddress((void**)&qTlo, g_qTlo);
    cudaGetSymbolAddress((void**)&Wthi, g_Wthi); cudaGetSymbolAddress((void**)&Wtlo, g_Wtlo);
    cudaGetSymbolAddress((void**)&pWhi, g_pWhi); cudaGetSymbolAddress((void**)&pWlo, g_pWlo);
    cudaGetSymbolAddress((void**)&Ehi, g_Ehi);   cudaGetSymbolAddress((void**)&Elo, g_Elo);
    cudaGetSymbolAddress((void**)&S, g_S);

    cudaFuncSetAttribute(gemm_mma<0>, cudaFuncAttributeMaxDynamicSharedMemorySize, SMEMSZ);
    cudaFuncSetAttribute(gemm_mma<1>, cudaFuncAttributeMaxDynamicSharedMemorySize, SMEMSZ);

    const dim3 ggrid(8, 8, 16);

    split2_kernel<<<16384, 256>>>(p, phi, plo);
    split_both_kernel<<<dim3(32, 32, 16), dim3(32, 8)>>>(q, qhi, qlo, qThi, qTlo);
    transpose_split_kernel<<<dim3(32, 32, 1), dim3(32, 8)>>>(W, Wthi, Wtlo);

    // GEMM1: pW = p @ W   (B = W^T K-major), split-store
    gemm_mma<1><<<ggrid, 512, SMEMSZ>>>(phi, plo, TT, Wthi, Wtlo, 0L,
                                        nullptr, pWhi, pWlo);
    // GEMM2: S = pW @ q^T -> fp32
    gemm_mma<0><<<ggrid, 512, SMEMSZ>>>(pWhi, pWlo, TT, qhi, qlo, TT,
                                        S, nullptr, nullptr);
    // fused: column softmax stats + exp + split
    softmax_exp_split<<<dim3(32, 16), 256>>>(S, Ehi, Elo);
    // GEMM3: out = E @ q  (B = q^T K-major) -> fp32
    gemm_mma<0><<<ggrid, 512, SMEMSZ>>>(Ehi, Elo, TT, qThi, qTlo, TT,
                                        out, nullptr, nullptr);
}

// round 7
// speedup vs baseline: 1.0477x; 1.0477x over previous
#include <cuda_runtime.h>
#include <cuda_bf16.h>
#include <cstdint>

// B=16, TQ=TP=DQ=DP=1024
// out = softmax_over_Tp((p@W)@q^T) @ q, fp32 in/out.
// GEMMs: mma.sync.m16n8k16 bf16, 2-way split, 3 products (hh+hl+lh).
// 128x128 CTA tile, K-chunk 32, hi/lo packed per 128B smem row, 3-stage cp.async,
// 256 threads (8 warps, 2m x 4n, 64x32 warp tiles), 2 CTAs/SM.

static const long TT = 1048576L;

// ---------------- scratch ----------------
__device__ __nv_bfloat16 g_qhi[16777216], g_qlo[16777216];
__device__ __nv_bfloat16 g_phi[16777216], g_plo[16777216];
__device__ __nv_bfloat16 g_qThi[16777216], g_qTlo[16777216];
__device__ __nv_bfloat16 g_Wthi[1048576],  g_Wtlo[1048576];
__device__ __nv_bfloat16 g_pWhi[16777216], g_pWlo[16777216];
__device__ __nv_bfloat16 g_Ehi[16777216],  g_Elo[16777216];
__device__ float g_S[16777216];

// ---------------- asm helpers ----------------
__device__ __forceinline__ uint32_t smem_u32(const void* p) {
    uint32_t a;
    asm("{ .reg .u64 t; cvta.to.shared.u64 t, %1; cvt.u32.u64 %0, t; }" : "=r"(a) : "l"(p));
    return a;
}
__device__ __forceinline__ void cp16(uint32_t s, const void* g) {
    asm volatile("cp.async.cg.shared.global [%0], [%1], 16;" :: "r"(s), "l"(g));
}
__device__ __forceinline__ void cp_commit() { asm volatile("cp.async.commit_group;"); }
template<int N>
__device__ __forceinline__ void cp_wait() { asm volatile("cp.async.wait_group %0;" :: "n"(N)); }

__device__ __forceinline__ void ldsm4(uint32_t (&r)[4], uint32_t a) {
    asm volatile("ldmatrix.sync.aligned.m8n8.x4.shared.b16 {%0,%1,%2,%3}, [%4];"
                 : "=r"(r[0]), "=r"(r[1]), "=r"(r[2]), "=r"(r[3]) : "r"(a));
}
__device__ __forceinline__ void mma16816(float (&d)[4], const uint32_t (&a)[4],
                                         uint32_t b0, uint32_t b1) {
    asm volatile(
        "mma.sync.aligned.m16n8k16.row.col.f32.bf16.bf16.f32 "
        "{%0,%1,%2,%3}, {%4,%5,%6,%7}, {%8,%9}, {%0,%1,%2,%3};"
        : "+f"(d[0]), "+f"(d[1]), "+f"(d[2]), "+f"(d[3])
        : "r"(a[0]), "r"(a[1]), "r"(a[2]), "r"(a[3]), "r"(b0), "r"(b1));
}

// ---------------- GEMM: C[b][m][n] = sum_k A[b][m][k] * B[b][n][k] ----------------
// Stage: A-tile 128 rows x [hi64B|lo64B] (16KB) + B-tile same (16KB) = 32KB.
static constexpr int MATB   = 128 * 128;   // 16KB packed hi/lo tile
static constexpr int STAGEB = 2 * MATB;    // 32KB
static constexpr int SMEMSZ = 3 * STAGEB;  // 96KB -> 2 CTAs/SM

template<int STORE_SPLIT>
__global__ void __launch_bounds__(256, 2)
gemm_mma(const __nv_bfloat16* __restrict__ Ahi, const __nv_bfloat16* __restrict__ Alo, long sA,
         const __nv_bfloat16* __restrict__ Bhi, const __nv_bfloat16* __restrict__ Blo, long sB,
         float* __restrict__ Cf, __nv_bfloat16* __restrict__ Chi, __nv_bfloat16* __restrict__ Clo)
{
    extern __shared__ char smem[];
    const uint32_t sbase = smem_u32(smem);
    const int tid = threadIdx.x, lane = tid & 31, wid = tid >> 5;
    const int wm = wid >> 2, wn = wid & 3;   // 2m x 4n, warp tile 64x32
    const int b = blockIdx.z, m0 = blockIdx.y * 128, n0 = blockIdx.x * 128;

    const char* gA[2] = { (const char*)(Ahi + (size_t)b * sA + (size_t)m0 * 1024),
                          (const char*)(Alo + (size_t)b * sA + (size_t)m0 * 1024) };
    const char* gB[2] = { (const char*)(Bhi + (size_t)b * sB + (size_t)n0 * 1024),
                          (const char*)(Blo + (size_t)b * sB + (size_t)n0 * 1024) };

    // loader: thread covers rows (tid>>2) and 64+(tid>>2), 16B col (tid&3) of the
    // 64B k-chunk, for hi (smem chunks 0-3) and lo (smem chunks 4-7) of A and B.
    const int lr0 = tid >> 2, lc = tid & 3;

    auto issue_stage = [&](int buf, int kt) {
        const uint32_t sb = sbase + buf * STAGEB;
        const size_t kb = (size_t)kt * 64;     // byte offset of K32 chunk in 2048B row
        #pragma unroll
        for (int m = 0; m < 2; m++) {          // A then B
            const uint32_t mb = sb + m * MATB;
            #pragma unroll
            for (int hl = 0; hl < 2; hl++) {
                const char* g = (m == 0) ? gA[hl] : gB[hl];
                #pragma unroll
                for (int t = 0; t < 2; t++) {
                    const int r = lr0 + t * 64;
                    const int c = lc + hl * 4;
                    cp16(mb + r * 128 + ((c ^ (r & 7)) * 16),
                         g + (size_t)r * 2048 + kb + lc * 16);
                }
            }
        }
        cp_commit();
    };

    float acc[4][4][4];
    #pragma unroll
    for (int i = 0; i < 4; i++)
        #pragma unroll
        for (int j = 0; j < 4; j++)
            #pragma unroll
            for (int t = 0; t < 4; t++) acc[i][j][t] = 0.f;

    issue_stage(0, 0);
    issue_stage(1, 1);

    // ldmatrix lane addressing
    const int lrow = lane & 15, lhi = lane >> 4;
    const int swz = lrow & 7;
    uint32_t kh[2], kl[2];
    #pragma unroll
    for (int ks = 0; ks < 2; ks++) {
        kh[ks] = (uint32_t)(((ks * 2 + lhi) ^ swz) * 16);
        kl[ks] = (uint32_t)(((ks * 2 + lhi + 4) ^ swz) * 16);
    }

    const uint32_t arow_off = (uint32_t)(wm * 64 + lrow) * 128;
    const uint32_t brow_off = (uint32_t)(wn * 32 + lrow) * 128;

    #pragma unroll 1
    for (int i = 0; i < 32; i++) {
        if (i < 31) cp_wait<1>(); else cp_wait<0>();
        __syncthreads();
        if (i + 2 < 32) issue_stage((i + 2) % 3, i + 2);

        const uint32_t sb = sbase + (i % 3) * STAGEB;
        const uint32_t sA_ = sb, sB_ = sb + MATB;

        #pragma unroll
        for (int ks = 0; ks < 2; ks++) {
            const uint32_t kbh = kh[ks], kbl = kl[ks];
            // product 1: hh
            uint32_t ah[4][4];
            #pragma unroll
            for (int mi = 0; mi < 4; mi++)
                ldsm4(ah[mi], sA_ + arow_off + (uint32_t)(mi * 16) * 128 + kbh);
            uint32_t bh[4][2];
            #pragma unroll
            for (int nj = 0; nj < 2; nj++) {
                uint32_t r[4];
                ldsm4(r, sB_ + brow_off + (uint32_t)(nj * 16) * 128 + kbh);
                bh[2*nj][0] = r[0]; bh[2*nj+1][0] = r[1];
                bh[2*nj][1] = r[2]; bh[2*nj+1][1] = r[3];
            }
            #pragma unroll
            for (int mi = 0; mi < 4; mi++)
                #pragma unroll
                for (int ni = 0; ni < 4; ni++)
                    mma16816(acc[mi][ni], ah[mi], bh[ni][0], bh[ni][1]);
            // product 2: hl (reuse ah)
            uint32_t bl[4][2];
            #pragma unroll
            for (int nj = 0; nj < 2; nj++) {
                uint32_t r[4];
                ldsm4(r, sB_ + brow_off + (uint32_t)(nj * 16) * 128 + kbl);
                bl[2*nj][0] = r[0]; bl[2*nj+1][0] = r[1];
                bl[2*nj][1] = r[2]; bl[2*nj+1][1] = r[3];
            }
            #pragma unroll
            for (int mi = 0; mi < 4; mi++)
                #pragma unroll
                for (int ni = 0; ni < 4; ni++)
                    mma16816(acc[mi][ni], ah[mi], bl[ni][0], bl[ni][1]);
            // product 3: lh (reuse bh)
            uint32_t al[4][4];
            #pragma unroll
            for (int mi = 0; mi < 4; mi++)
                ldsm4(al[mi], sA_ + arow_off + (uint32_t)(mi * 16) * 128 + kbl);
            #pragma unroll
            for (int mi = 0; mi < 4; mi++)
                #pragma unroll
                for (int ni = 0; ni < 4; ni++)
                    mma16816(acc[mi][ni], al[mi], bh[ni][0], bh[ni][1]);
        }
    }

    // epilogue
    const int er = m0 + wm * 64 + (lane >> 2);
    const int ec = n0 + wn * 32 + (lane & 3) * 2;
    #pragma unroll
    for (int mi = 0; mi < 4; mi++)
        #pragma unroll
        for (int ni = 0; ni < 4; ni++) {
            const int r0 = er + mi * 16, c = ec + ni * 8;
            const size_t o0 = (size_t)b * TT + (size_t)r0 * 1024 + c;
            const size_t o1 = o0 + 8 * 1024;
            if (STORE_SPLIT == 0) {
                *(float2*)(Cf + o0) = make_float2(acc[mi][ni][0], acc[mi][ni][1]);
                *(float2*)(Cf + o1) = make_float2(acc[mi][ni][2], acc[mi][ni][3]);
            } else {
                #pragma unroll
                for (int h = 0; h < 2; h++) {
                    const size_t o = h ? o1 : o0;
                    float x0 = acc[mi][ni][2*h], x1 = acc[mi][ni][2*h+1];
                    __nv_bfloat16 h0 = __float2bfloat16(x0);
                    __nv_bfloat16 h1 = __float2bfloat16(x1);
                    __nv_bfloat16 l0 = __float2bfloat16(x0 - __bfloat162float(h0));
                    __nv_bfloat16 l1 = __float2bfloat16(x1 - __bfloat162float(h1));
                    __nv_bfloat162 hp; hp.x = h0; hp.y = h1;
                    __nv_bfloat162 lp; lp.x = l0; lp.y = l1;
                    *(__nv_bfloat162*)(Chi + o) = hp;
                    *(__nv_bfloat162*)(Clo + o) = lp;
                }
            }
        }
}

// ---------------- elementwise / transpose / softmax ----------------
struct alignas(8) bh4 { __nv_bfloat16 a, b, c, d; };

__device__ __forceinline__ void split1(float x, __nv_bfloat16& h, __nv_bfloat16& l) {
    h = __float2bfloat16(x);
    l = __float2bfloat16(x - __bfloat162float(h));
}

__global__ void __launch_bounds__(256)
split2_kernel(const float* __restrict__ X, __nv_bfloat16* __restrict__ hi,
              __nv_bfloat16* __restrict__ lo)
{
    size_t i = (size_t)blockIdx.x * 256 + threadIdx.x;
    float4 v = ((const float4*)X)[i];
    bh4 h, l;
    split1(v.x, h.a, l.a); split1(v.y, h.b, l.b);
    split1(v.z, h.c, l.c); split1(v.w, h.d, l.d);
    ((bh4*)hi)[i] = h;
    ((bh4*)lo)[i] = l;
}

__global__ void __launch_bounds__(256)
split_both_kernel(const float* __restrict__ in,
                  __nv_bfloat16* __restrict__ ohi, __nv_bfloat16* __restrict__ olo,
                  __nv_bfloat16* __restrict__ thi, __nv_bfloat16* __restrict__ tlo)
{
    __shared__ float t[32][33];
    const int b = blockIdx.z;
    const float* I = in + (size_t)b * TT;
    const int x = blockIdx.x * 32 + threadIdx.x;
    const int y = blockIdx.y * 32 + threadIdx.y;
    const size_t ob = (size_t)b * TT;
    #pragma unroll
    for (int j = 0; j < 32; j += 8) {
        float v = I[(size_t)(y + j) * 1024 + x];
        t[threadIdx.y + j][threadIdx.x] = v;
        __nv_bfloat16 h, l; split1(v, h, l);
        ohi[ob + (size_t)(y + j) * 1024 + x] = h;
        olo[ob + (size_t)(y + j) * 1024 + x] = l;
    }
    __syncthreads();
    const int ox = blockIdx.y * 32 + threadIdx.x;
    const int oy = blockIdx.x * 32 + threadIdx.y;
    #pragma unroll
    for (int j = 0; j < 32; j += 8) {
        float v = t[threadIdx.x][threadIdx.y + j];
        __nv_bfloat16 h, l; split1(v, h, l);
        thi[ob + (size_t)(oy + j) * 1024 + ox] = h;
        tlo[ob + (size_t)(oy + j) * 1024 + ox] = l;
    }
}

__global__ void __launch_bounds__(256)
transpose_split_kernel(const float* __restrict__ in, __nv_bfloat16* __restrict__ ohi,
                       __nv_bfloat16* __restrict__ olo)
{
    __shared__ float t[32][33];
    const int b = blockIdx.z;
    const float* I = in + (size_t)b * TT;
    const int x = blockIdx.x * 32 + threadIdx.x;
    const int y = blockIdx.y * 32 + threadIdx.y;
    #pragma unroll
    for (int j = 0; j < 32; j += 8)
        t[threadIdx.y + j][threadIdx.x] = I[(size_t)(y + j) * 1024 + x];
    __syncthreads();
    const int ox = blockIdx.y * 32 + threadIdx.x;
    const int oy = blockIdx.x * 32 + threadIdx.y;
    const size_t ob = (size_t)b * TT;
    #pragma unroll
    for (int j = 0; j < 32; j += 8) {
        float v = t[threadIdx.x][threadIdx.y + j];
        __nv_bfloat16 h, l; split1(v, h, l);
        ohi[ob + (size_t)(oy + j) * 1024 + ox] = h;
        olo[ob + (size_t)(oy + j) * 1024 + ox] = l;
    }
}

// Fused column softmax (over Tp = rows of S[b]) + exp + bf16 split.
__global__ void __launch_bounds__(256)
softmax_exp_split(const float* __restrict__ S,
                  __nv_bfloat16* __restrict__ Ehi, __nv_bfloat16* __restrict__ Elo)
{
    __shared__ float sm[8][32], sz[8][32];
    __shared__ float fm[32], fz[32];
    const int b = blockIdx.y;
    const int c = (threadIdx.x & 31);
    const int g = threadIdx.x >> 5;
    const int col = blockIdx.x * 32 + c;
    const float* Sb = S + (size_t)b * TT + col;

    float m = -1e30f, z = 0.f;
    #pragma unroll 4
    for (int r = g; r < 1024; r += 8) {
        float x = Sb[(size_t)r << 10];
        if (x > m) { z = z * __expf(m - x) + 1.f; m = x; }
        else       { z += __expf(x - m); }
    }
    sm[g][c] = m; sz[g][c] = z;
    __syncthreads();
    if (threadIdx.x < 32) {
        float M = sm[0][c];
        #pragma unroll
        for (int i = 1; i < 8; i++) M = fmaxf(M, sm[i][c]);
        float Z = 0.f;
        #pragma unroll
        for (int i = 0; i < 8; i++) Z += sz[i][c] * __expf(sm[i][c] - M);
        fm[c] = M; fz[c] = 1.0f / Z;
    }
    __syncthreads();
    const float Mf = fm[c], Rf = fz[c];
    __nv_bfloat16* eh = Ehi + (size_t)b * TT + col;
    __nv_bfloat16* el = Elo + (size_t)b * TT + col;
    #pragma unroll 4
    for (int r = g; r < 1024; r += 8) {
        float x = Sb[(size_t)r << 10];
        float w = __expf(x - Mf) * Rf;
        __nv_bfloat16 h, l; split1(w, h, l);
        eh[(size_t)r << 10] = h;
        el[(size_t)r << 10] = l;
    }
}

// ---------------- launcher ----------------
extern "C" void kernel_launch(void* const* d_in, const int* in_sizes, int n_in,
                              void* d_out, int out_size)
{
    const float* q = (const float*)d_in[0];
    const float* p = (const float*)d_in[1];
    const float* W = (const float*)d_in[2];
    float* out = (float*)d_out;

    __nv_bfloat16 *qhi, *qlo, *phi, *plo, *qThi, *qTlo, *Wthi, *Wtlo, *pWhi, *pWlo, *Ehi, *Elo;
    float *S;
    cudaGetSymbolAddress((void**)&qhi, g_qhi);   cudaGetSymbolAddress((void**)&qlo, g_qlo);
    cudaGetSymbolAddress((void**)&phi, g_phi);   cudaGetSymbolAddress((void**)&plo, g_plo);
    cudaGetSymbolAddress((void**)&qThi, g_qThi); cudaGetSymbolAddress((void**)&qTlo, g_qTlo);
    cudaGetSymbolAddress((void**)&Wthi, g_Wthi); cudaGetSymbolAddress((void**)&Wtlo, g_Wtlo);
    cudaGetSymbolAddress((void**)&pWhi, g_pWhi); cudaGetSymbolAddress((void**)&pWlo, g_pWlo);
    cudaGetSymbolAddress((void**)&Ehi, g_Ehi);   cudaGetSymbolAddress((void**)&Elo, g_Elo);
    cudaGetSymbolAddress((void**)&S, g_S);

    cudaFuncSetAttribute(gemm_mma<0>, cudaFuncAttributeMaxDynamicSharedMemorySize, SMEMSZ);
    cudaFuncSetAttribute(gemm_mma<1>, cudaFuncAttributeMaxDynamicSharedMemorySize, SMEMSZ);

    const dim3 ggrid(8, 8, 16);

    split2_kernel<<<16384, 256>>>(p, phi, plo);
    split_both_kernel<<<dim3(32, 32, 16), dim3(32, 8)>>>(q, qhi, qlo, qThi, qTlo);
    transpose_split_kernel<<<dim3(32, 32, 1), dim3(32, 8)>>>(W, Wthi, Wtlo);

    // GEMM1: pW = p @ W   (B = W^T K-major), split-store
    gemm_mma<1><<<ggrid, 256, SMEMSZ>>>(phi, plo, TT, Wthi, Wtlo, 0L,
                                        nullptr, pWhi, pWlo);
    // GEMM2: S = pW @ q^T -> fp32
    gemm_mma<0><<<ggrid, 256, SMEMSZ>>>(pWhi, pWlo, TT, qhi, qlo, TT,
                                        S, nullptr, nullptr);
    // fused: column softmax stats + exp + split
    softmax_exp_split<<<dim3(32, 16), 256>>>(S, Ehi, Elo);
    // GEMM3: out = E @ q  (B = q^T K-major) -> fp32
    gemm_mma<0><<<ggrid, 256, SMEMSZ>>>(Ehi, Elo, TT, qThi, qTlo, TT,
                                        out, nullptr, nullptr);
}